// round 10
// baseline (speedup 1.0000x reference)
#include <cuda_runtime.h>
#include <cuda_fp16.h>
#include <cstdint>

#define N_NODES 50000
#define HD 128
#define E_MAX 600000
#define CSR_BLOCKS 148
#define CSR_THREADS 512

// ---------------- scratch (device globals; no dynamic allocation) ----------
__device__ float  g_dis[N_NODES];                 // rsqrt(degree incl. self-loop)
__device__ int    g_cnt[N_NODES];                 // in-degree histogram (edges only)
__device__ int    g_rowptr[N_NODES + 1];          // CSR row pointers
__device__ int    g_cursor[N_NODES];              // fill cursors
__device__ int    g_bsum[512];                    // per-chunk sums
__device__ int    g_bsumx[512];                   // exclusive-scanned chunk sums
__device__ int2   g_csr[E_MAX];                   // packed (src, norm), dst-sorted
__device__ float  g_xw[(size_t)N_NODES * HD];     // x @ W^T (fp32)
__device__ __half g_xwh[(size_t)N_NODES * HD];    // x @ W^T (fp16, for gathers)
__device__ float  g_h1[(size_t)N_NODES * HD];     // layer-1 output
__device__ int    g_is64;                         // 1 if edge_index stored as int64

// Monotonic grid barrier state (never reset => safe across graph replays).
__device__ unsigned g_bcount = 0;
__device__ volatile unsigned g_bphase = 0;

struct __align__(8) h4 { __half2 a, b; };

static __device__ __forceinline__ void gbar(unsigned& my) {
    __syncthreads();
    if (threadIdx.x == 0) {
        __threadfence();
        my += 1;
        unsigned c = atomicAdd(&g_bcount, 1) + 1;
        if (c == CSR_BLOCKS * my) {
            g_bphase = my;
        } else {
            while (g_bphase < my) { }
            __threadfence();
        }
    }
    __syncthreads();
}

// ---------------- fused CSR build: one persistent kernel --------------------
// ph0 init cnt + detect width; ph1 histogram; ph2 per-chunk scan (+dis);
// ph3 chunk-sum scan; ph4 apply offsets; ph5 fill CSR.
__global__ void __launch_bounds__(CSR_THREADS, 1)
csr_build_kernel(const int* __restrict__ ew, int n, int E)
{
    __shared__ int sm[CSR_THREADS];
    const int tid  = threadIdx.x;
    const int bid  = blockIdx.x;
    const int gtid = bid * CSR_THREADS + tid;
    const int gstride = CSR_BLOCKS * CSR_THREADS;   // 75776
    unsigned my = g_bphase;   // stable pre-launch value, same for all blocks

    // ---- ph0: zero histogram; block 0 detects index width ----
    for (int i = gtid; i < n; i += gstride) g_cnt[i] = 0;
    if (bid == 0) {
        __shared__ int found;
        if (tid == 0) found = 0;
        __syncthreads();
        int f = 0;
        for (int j = tid; j < 2048; j += CSR_THREADS)
            if (ew[2 * j + 1] != 0) f = 1;
        if (f) atomicOr(&found, 1);
        __syncthreads();
        if (tid == 0) g_is64 = found ? 0 : 1;
    }
    gbar(my);

    // ---- ph1: histogram of destinations ----
    {
        int is64 = __ldcg(&g_is64);
        for (int e = gtid; e < E; e += gstride) {
            int d = is64 ? ew[2 * (E + e)] : ew[E + e];
            atomicAdd(&g_cnt[d], 1);
        }
    }
    gbar(my);

    // ---- ph2: per-chunk (512) inclusive scan -> local-exclusive rowptr ----
    const int NCH = (n + CSR_THREADS - 1) / CSR_THREADS;   // 98
    if (bid < NCH) {
        int i = bid * CSR_THREADS + tid;
        int v = (i < n) ? __ldcg(&g_cnt[i]) : 0;
        if (i < n) g_dis[i] = rsqrtf((float)(v + 1));
        sm[tid] = v;
        __syncthreads();
        #pragma unroll
        for (int off = 1; off < CSR_THREADS; off <<= 1) {
            int t = (tid >= off) ? sm[tid - off] : 0;
            __syncthreads();
            sm[tid] += t;
            __syncthreads();
        }
        if (i < n) g_rowptr[i] = sm[tid] - v;
        if (tid == CSR_THREADS - 1) g_bsum[bid] = sm[tid];
    }
    gbar(my);

    // ---- ph3: block 0 scans chunk sums (exclusive) ----
    if (bid == 0) {
        int v = (tid < NCH) ? __ldcg(&g_bsum[tid]) : 0;
        sm[tid] = v;
        __syncthreads();
        #pragma unroll
        for (int off = 1; off < CSR_THREADS; off <<= 1) {
            int t = (tid >= off) ? sm[tid - off] : 0;
            __syncthreads();
            sm[tid] += t;
            __syncthreads();
        }
        if (tid < NCH) g_bsumx[tid] = sm[tid] - v;
    }
    gbar(my);

    // ---- ph4: apply chunk offsets; init cursors ----
    if (bid < NCH) {
        int i = bid * CSR_THREADS + tid;
        if (i < n) {
            int rp = g_rowptr[i] + __ldcg(&g_bsumx[bid]);  // rowptr written by this block
            g_rowptr[i] = rp;
            g_cursor[i] = rp;
        }
    }
    if (bid == 0 && tid == 0) g_rowptr[n] = E;
    gbar(my);

    // ---- ph5: fill CSR (src, norm) ----
    {
        int is64 = __ldcg(&g_is64);
        for (int e = gtid; e < E; e += gstride) {
            int s, d;
            if (is64) { s = ew[2 * e]; d = ew[2 * (E + e)]; }
            else      { s = ew[e];     d = ew[E + e]; }
            float nm = __ldcg(&g_dis[s]) * __ldcg(&g_dis[d]);
            int pos = atomicAdd(&g_cursor[d], 1);
            g_csr[pos] = make_int2(s, __float_as_int(nm));
        }
    }
}

// ---------------- GEMM: XW = X @ W^T (SIMT, packed f32x2) ------------------
#define GEMM_SMEM_BYTES ((128 * 129 + 128 * 128) * 4)   // ~131.5 KB

__global__ void __launch_bounds__(256, 1)
gcn_gemm(const float* __restrict__ X, const float* __restrict__ W,
         float* __restrict__ XW, __half* __restrict__ XWH, int nrows)
{
    extern __shared__ float sm[];
    float* Xs = sm;               // [128][129] padded
    float* Wt = sm + 128 * 129;   // Wt[k][c] = W[c][k]

    const int tid  = threadIdx.x;
    const int row0 = blockIdx.x * 128;

    #pragma unroll
    for (int i = tid; i < 128 * 32; i += 256) {
        int c = i >> 5, kq = i & 31;
        float4 w4 = *((const float4*)W + c * 32 + kq);
        int k = kq << 2;
        Wt[(k + 0) * 128 + c] = w4.x;
        Wt[(k + 1) * 128 + c] = w4.y;
        Wt[(k + 2) * 128 + c] = w4.z;
        Wt[(k + 3) * 128 + c] = w4.w;
    }
    #pragma unroll
    for (int i = tid; i < 128 * 32; i += 256) {
        int r = i >> 5, kq = i & 31;
        int gr = row0 + r;
        float4 v = make_float4(0.f, 0.f, 0.f, 0.f);
        if (gr < nrows) v = *((const float4*)X + (size_t)gr * 32 + kq);
        float* p = &Xs[r * 129 + (kq << 2)];
        p[0] = v.x; p[1] = v.y; p[2] = v.z; p[3] = v.w;
    }
    __syncthreads();

    const int tx = tid & 15;
    const int ty = tid >> 4;
    const int c0 = tx * 8;
    const float* xb = &Xs[(ty * 8) * 129];

    unsigned long long acc[8][4];
    #pragma unroll
    for (int r = 0; r < 8; r++)
        #pragma unroll
        for (int j = 0; j < 4; j++) acc[r][j] = 0ull;

    #pragma unroll 4
    for (int k = 0; k < 128; k++) {
        const ulonglong2* wrow = (const ulonglong2*)&Wt[k * 128 + c0];
        ulonglong2 wa = wrow[0], wb = wrow[1];
        #pragma unroll
        for (int r = 0; r < 8; r++) {
            float xv = xb[r * 129 + k];
            unsigned long long xx;
            asm("mov.b64 %0, {%1, %1};" : "=l"(xx) : "f"(xv));
            asm("fma.rn.f32x2 %0, %1, %2, %0;" : "+l"(acc[r][0]) : "l"(xx), "l"(wa.x));
            asm("fma.rn.f32x2 %0, %1, %2, %0;" : "+l"(acc[r][1]) : "l"(xx), "l"(wa.y));
            asm("fma.rn.f32x2 %0, %1, %2, %0;" : "+l"(acc[r][2]) : "l"(xx), "l"(wb.x));
            asm("fma.rn.f32x2 %0, %1, %2, %0;" : "+l"(acc[r][3]) : "l"(xx), "l"(wb.y));
        }
    }

    #pragma unroll
    for (int r = 0; r < 8; r++) {
        int gr = row0 + ty * 8 + r;
        if (gr >= nrows) break;
        float v[8];
        #pragma unroll
        for (int j = 0; j < 4; j++) {
            float lo, hi;
            asm("mov.b64 {%0, %1}, %2;" : "=f"(lo), "=f"(hi) : "l"(acc[r][j]));
            v[2 * j] = lo; v[2 * j + 1] = hi;
        }
        float4* xwp = (float4*)&XW[(size_t)gr * HD + c0];
        xwp[0] = make_float4(v[0], v[1], v[2], v[3]);
        xwp[1] = make_float4(v[4], v[5], v[6], v[7]);
        h4* xhp = (h4*)&XWH[(size_t)gr * HD + c0];
        h4 h0, h1;
        h0.a = __floats2half2_rn(v[0], v[1]);
        h0.b = __floats2half2_rn(v[2], v[3]);
        h1.a = __floats2half2_rn(v[4], v[5]);
        h1.b = __floats2half2_rn(v[6], v[7]);
        xhp[0] = h0; xhp[1] = h1;
    }
}

// ---------------- aggregation ------------------------------------------------
// out[d] = b + dis[d]^2 * xw[d] + sum norm_e * xwh[src_e]   (gathers in fp16)
__global__ void __launch_bounds__(256)
aggregate_kernel(const float* __restrict__ bias,
                 const float* __restrict__ xw,
                 const __half* __restrict__ xwh,
                 float* __restrict__ out, int n)
{
    int node = blockIdx.x * 8 + (threadIdx.x >> 5);
    int lane = threadIdx.x & 31;
    if (node >= n) return;

    int beg = g_rowptr[node];
    int end = g_rowptr[node + 1];

    float ds = g_dis[node];
    float sc = ds * ds;
    float4 vs = ((const float4*)(xw + (size_t)node * HD))[lane];
    float4 b4 = ((const float4*)bias)[lane];
    float4 acc;
    acc.x = fmaf(sc, vs.x, b4.x);
    acc.y = fmaf(sc, vs.y, b4.y);
    acc.z = fmaf(sc, vs.z, b4.z);
    acc.w = fmaf(sc, vs.w, b4.w);

    int p = beg;
    for (; p + 4 <= end; p += 4) {
        int2 e0 = g_csr[p + 0];
        int2 e1 = g_csr[p + 1];
        int2 e2 = g_csr[p + 2];
        int2 e3 = g_csr[p + 3];
        h4 h0 = ((const h4*)(xwh + (size_t)e0.x * HD))[lane];
        h4 h1 = ((const h4*)(xwh + (size_t)e1.x * HD))[lane];
        h4 h2 = ((const h4*)(xwh + (size_t)e2.x * HD))[lane];
        h4 h3 = ((const h4*)(xwh + (size_t)e3.x * HD))[lane];
        float n0 = __int_as_float(e0.y), n1 = __int_as_float(e1.y);
        float n2 = __int_as_float(e2.y), n3 = __int_as_float(e3.y);
        float2 a0 = __half22float2(h0.a), b0 = __half22float2(h0.b);
        float2 a1 = __half22float2(h1.a), b1 = __half22float2(h1.b);
        float2 a2 = __half22float2(h2.a), b2 = __half22float2(h2.b);
        float2 a3 = __half22float2(h3.a), b3 = __half22float2(h3.b);
        acc.x = fmaf(n0, a0.x, acc.x); acc.y = fmaf(n0, a0.y, acc.y);
        acc.z = fmaf(n0, b0.x, acc.z); acc.w = fmaf(n0, b0.y, acc.w);
        acc.x = fmaf(n1, a1.x, acc.x); acc.y = fmaf(n1, a1.y, acc.y);
        acc.z = fmaf(n1, b1.x, acc.z); acc.w = fmaf(n1, b1.y, acc.w);
        acc.x = fmaf(n2, a2.x, acc.x); acc.y = fmaf(n2, a2.y, acc.y);
        acc.z = fmaf(n2, b2.x, acc.z); acc.w = fmaf(n2, b2.y, acc.w);
        acc.x = fmaf(n3, a3.x, acc.x); acc.y = fmaf(n3, a3.y, acc.y);
        acc.z = fmaf(n3, b3.x, acc.z); acc.w = fmaf(n3, b3.y, acc.w);
    }
    for (; p < end; p++) {
        int2 e = g_csr[p];
        h4 hv = ((const h4*)(xwh + (size_t)e.x * HD))[lane];
        float nm = __int_as_float(e.y);
        float2 fa = __half22float2(hv.a), fb = __half22float2(hv.b);
        acc.x = fmaf(nm, fa.x, acc.x); acc.y = fmaf(nm, fa.y, acc.y);
        acc.z = fmaf(nm, fb.x, acc.z); acc.w = fmaf(nm, fb.y, acc.w);
    }

    ((float4*)(out + (size_t)node * HD))[lane] = acc;
}

// ---------------- launch ----------------------------------------------------
extern "C" void kernel_launch(void* const* d_in, const int* in_sizes, int n_in,
                              void* d_out, int out_size) {
    const float* emb = (const float*)d_in[0];
    const int*   ew  = (const int*)d_in[1];   // width detected on device
    const float* W1  = (const float*)d_in[2];
    const float* b1  = (const float*)d_in[3];
    const float* W2  = (const float*)d_in[4];
    const float* b2  = (const float*)d_in[5];
    float* out = (float*)d_out;

    const int nrows = in_sizes[0] / HD;       // 50000
    const int E     = in_sizes[1] / 2;        // 600000

    float *xw_p, *h1_p;
    __half* xwh_p;
    cudaGetSymbolAddress((void**)&xw_p,  g_xw);
    cudaGetSymbolAddress((void**)&xwh_p, g_xwh);
    cudaGetSymbolAddress((void**)&h1_p,  g_h1);

    cudaFuncSetAttribute(gcn_gemm, cudaFuncAttributeMaxDynamicSharedMemorySize,
                         GEMM_SMEM_BYTES);

    // Side stream + events (created once on the first, non-captured call).
    static cudaStream_t s_side = nullptr;
    static cudaEvent_t  s_ev0 = nullptr, s_ev1 = nullptr;
    if (s_side == nullptr) {
        cudaStreamCreateWithFlags(&s_side, cudaStreamNonBlocking);
        cudaEventCreateWithFlags(&s_ev0, cudaEventDisableTiming);
        cudaEventCreateWithFlags(&s_ev1, cudaEventDisableTiming);
    }

    const int nb_gemm = (nrows + 127) / 128;   // 391
    const int nb_agg  = (nrows + 7) / 8;       // 6250

    // ---- fork: layer-1 GEMM on side stream, fused CSR build on main ----
    cudaEventRecord(s_ev0, 0);
    cudaStreamWaitEvent(s_side, s_ev0, 0);
    gcn_gemm<<<nb_gemm, 256, GEMM_SMEM_BYTES, s_side>>>(emb, W1, xw_p, xwh_p, nrows);
    cudaEventRecord(s_ev1, s_side);

    csr_build_kernel<<<CSR_BLOCKS, CSR_THREADS>>>(ew, nrows, E);

    // ---- join, then serial tail ----
    cudaStreamWaitEvent(0, s_ev1, 0);
    aggregate_kernel<<<nb_agg, 256>>>(b1, xw_p, xwh_p, h1_p, nrows);
    gcn_gemm<<<nb_gemm, 256, GEMM_SMEM_BYTES>>>(h1_p, W2, xw_p, xwh_p, nrows);
    aggregate_kernel<<<nb_agg, 256>>>(b2, xw_p, xwh_p, out, nrows);
}

// round 11
// speedup vs baseline: 1.2558x; 1.2558x over previous
#include <cuda_runtime.h>
#include <cuda_fp16.h>
#include <cstdint>

#define N_NODES 50000
#define HD 128
#define E_MAX 600000

// ---------------- scratch (device globals; no dynamic allocation) ----------
__device__ float  g_dis[N_NODES];                 // rsqrt(degree incl. self-loop)
__device__ int    g_cnt[N_NODES];                 // in-degree histogram (edges only)
__device__ int    g_rowptr[N_NODES + 1];          // CSR row pointers
__device__ int    g_cursor[N_NODES];              // fill cursors
__device__ int    g_bsum[256];                    // scan block sums
__device__ int2   g_csr[E_MAX];                   // packed (src, norm), dst-sorted
__device__ float  g_xw[(size_t)N_NODES * HD];     // x @ W^T (fp32)
__device__ __half g_xwh[(size_t)N_NODES * HD];    // x @ W^T (fp16, for gathers)
__device__ float  g_h1[(size_t)N_NODES * HD];     // layer-1 output
__device__ int    g_is64;                         // 1 if edge_index stored as int64

struct __align__(8) h4 { __half2 a, b; };

// ---------------- init + dtype detect (merged) ------------------------------
__global__ void initdetect_kernel(const int* __restrict__ ew, int n) {
    int i = blockIdx.x * blockDim.x + threadIdx.x;
    if (i < n) g_cnt[i] = 0;
    if (blockIdx.x == 0) {
        __shared__ int found;
        if (threadIdx.x == 0) found = 0;
        __syncthreads();
        int f = 0;
        for (int j = threadIdx.x; j < 2048; j += blockDim.x)
            if (ew[2 * j + 1] != 0) f = 1;
        if (f) atomicOr(&found, 1);
        __syncthreads();
        if (threadIdx.x == 0) g_is64 = found ? 0 : 1;
    }
}

__global__ void hist_kernel(const int* __restrict__ ew, int E) {
    int e = blockIdx.x * blockDim.x + threadIdx.x;
    if (e >= E) return;
    int d = g_is64 ? ew[2 * (E + e)] : ew[E + e];
    atomicAdd(&g_cnt[d], 1);
}

// ---- exclusive scan of g_cnt -> g_rowptr (3 kernels); also emits g_dis ----
__global__ void scanA_kernel(int n) {
    __shared__ int sm[256];
    int i = blockIdx.x * 256 + threadIdx.x;
    int v = (i < n) ? g_cnt[i] : 0;
    if (i < n) g_dis[i] = rsqrtf((float)(v + 1));
    sm[threadIdx.x] = v;
    __syncthreads();
    #pragma unroll
    for (int off = 1; off < 256; off <<= 1) {
        int t = (threadIdx.x >= off) ? sm[threadIdx.x - off] : 0;
        __syncthreads();
        sm[threadIdx.x] += t;
        __syncthreads();
    }
    if (i < n) g_rowptr[i] = sm[threadIdx.x] - v;
    if (threadIdx.x == 255) g_bsum[blockIdx.x] = sm[255];
}

__global__ void scanB_kernel(int nb) {
    __shared__ int sm[256];
    int v = (threadIdx.x < nb) ? g_bsum[threadIdx.x] : 0;
    sm[threadIdx.x] = v;
    __syncthreads();
    #pragma unroll
    for (int off = 1; off < 256; off <<= 1) {
        int t = (threadIdx.x >= off) ? sm[threadIdx.x - off] : 0;
        __syncthreads();
        sm[threadIdx.x] += t;
        __syncthreads();
    }
    if (threadIdx.x < nb) g_bsum[threadIdx.x] = sm[threadIdx.x] - v;
}

__global__ void scanC_kernel(int n, int E) {
    int i = blockIdx.x * 256 + threadIdx.x;
    if (i < n) {
        int rp = g_rowptr[i] + g_bsum[blockIdx.x];
        g_rowptr[i] = rp;
        g_cursor[i] = rp;
    }
    if (i == 0) g_rowptr[n] = E;
}

__global__ void fill_kernel(const int* __restrict__ ew, int E) {
    int e = blockIdx.x * blockDim.x + threadIdx.x;
    if (e >= E) return;
    int s, d;
    if (g_is64) { s = ew[2 * e]; d = ew[2 * (E + e)]; }
    else        { s = ew[e];     d = ew[E + e]; }
    int pos = atomicAdd(&g_cursor[d], 1);
    float nm = g_dis[s] * g_dis[d];
    g_csr[pos] = make_int2(s, __float_as_int(nm));
}

// ---------------- GEMM: XW = X @ W^T (SIMT, packed f32x2, k-tiled) ---------
// 128 rows x 128 cols per CTA, 256 threads, 8x8 reg tile, KT=64 k-tiles.
// Xd holds (x,x) dup pairs (ull), one LDS.128 serves 2 k's; W transposed.
// 2 CTAs/SM (smem ~98KB, regs capped at 128 by launch_bounds).
#define KT 64
#define XD_STRIDE 66                              // ull per row (64 + 2 pad)
#define GEMM_SMEM_BYTES (128 * XD_STRIDE * 8 + KT * 128 * 4)   // 100,352 B

__global__ void __launch_bounds__(256, 2)
gcn_gemm(const float* __restrict__ X, const float* __restrict__ W,
         float* __restrict__ XW, __half* __restrict__ XWH, int nrows)
{
    extern __shared__ char smraw[];
    unsigned long long* Xd = (unsigned long long*)smraw;     // [128][XD_STRIDE]
    float* Wt = (float*)(smraw + 128 * XD_STRIDE * 8);       // [KT][128]

    const int tid  = threadIdx.x;
    const int row0 = blockIdx.x * 128;
    const int tx = tid & 15;
    const int ty = tid >> 4;
    const int c0 = tx * 8;

    unsigned long long acc[8][4];
    #pragma unroll
    for (int r = 0; r < 8; r++)
        #pragma unroll
        for (int j = 0; j < 4; j++) acc[r][j] = 0ull;

    #pragma unroll
    for (int t = 0; t < 2; t++) {
        const int k0 = t * KT;

        // W tile transposed: Wt[kk][c] = W[c][k0+kk]
        #pragma unroll
        for (int i = tid; i < 128 * (KT / 4); i += 256) {    // 2048, 8 iters
            int c = i & 127, kq = i >> 7;                    // kq 0..15
            float4 w4 = ((const float4*)W)[c * 32 + (k0 >> 2) + kq];
            Wt[(4 * kq + 0) * 128 + c] = w4.x;
            Wt[(4 * kq + 1) * 128 + c] = w4.y;
            Wt[(4 * kq + 2) * 128 + c] = w4.z;
            Wt[(4 * kq + 3) * 128 + c] = w4.w;
        }
        // X tile, duplicated pairs: Xd[r][kk] = {x, x}
        #pragma unroll
        for (int i = tid; i < 128 * (KT / 4); i += 256) {
            int r = i >> 4, kq = i & 15;
            int gr = row0 + r;
            float4 v = make_float4(0.f, 0.f, 0.f, 0.f);
            if (gr < nrows) v = ((const float4*)X)[(size_t)gr * 32 + (k0 >> 2) + kq];
            unsigned long long d0, d1, d2, d3;
            asm("mov.b64 %0, {%1, %1};" : "=l"(d0) : "f"(v.x));
            asm("mov.b64 %0, {%1, %1};" : "=l"(d1) : "f"(v.y));
            asm("mov.b64 %0, {%1, %1};" : "=l"(d2) : "f"(v.z));
            asm("mov.b64 %0, {%1, %1};" : "=l"(d3) : "f"(v.w));
            unsigned long long* p = &Xd[r * XD_STRIDE + 4 * kq];
            p[0] = d0; p[1] = d1; p[2] = d2; p[3] = d3;
        }
        __syncthreads();

        const unsigned long long* xb = &Xd[(ty * 8) * XD_STRIDE];

        #pragma unroll 4
        for (int kk = 0; kk < KT; kk += 2) {
            const ulonglong2* w0p = (const ulonglong2*)&Wt[kk * 128 + c0];
            const ulonglong2* w1p = (const ulonglong2*)&Wt[(kk + 1) * 128 + c0];
            ulonglong2 w0a = w0p[0], w0b = w0p[1];
            ulonglong2 w1a = w1p[0], w1b = w1p[1];
            #pragma unroll
            for (int r = 0; r < 8; r++) {
                ulonglong2 xp = *(const ulonglong2*)&xb[r * XD_STRIDE + kk];
                asm("fma.rn.f32x2 %0, %1, %2, %0;" : "+l"(acc[r][0]) : "l"(xp.x), "l"(w0a.x));
                asm("fma.rn.f32x2 %0, %1, %2, %0;" : "+l"(acc[r][1]) : "l"(xp.x), "l"(w0a.y));
                asm("fma.rn.f32x2 %0, %1, %2, %0;" : "+l"(acc[r][2]) : "l"(xp.x), "l"(w0b.x));
                asm("fma.rn.f32x2 %0, %1, %2, %0;" : "+l"(acc[r][3]) : "l"(xp.x), "l"(w0b.y));
                asm("fma.rn.f32x2 %0, %1, %2, %0;" : "+l"(acc[r][0]) : "l"(xp.y), "l"(w1a.x));
                asm("fma.rn.f32x2 %0, %1, %2, %0;" : "+l"(acc[r][1]) : "l"(xp.y), "l"(w1a.y));
                asm("fma.rn.f32x2 %0, %1, %2, %0;" : "+l"(acc[r][2]) : "l"(xp.y), "l"(w1b.x));
                asm("fma.rn.f32x2 %0, %1, %2, %0;" : "+l"(acc[r][3]) : "l"(xp.y), "l"(w1b.y));
            }
        }
        __syncthreads();
    }

    #pragma unroll
    for (int r = 0; r < 8; r++) {
        int gr = row0 + ty * 8 + r;
        if (gr >= nrows) break;
        float v[8];
        #pragma unroll
        for (int j = 0; j < 4; j++) {
            float lo, hi;
            asm("mov.b64 {%0, %1}, %2;" : "=f"(lo), "=f"(hi) : "l"(acc[r][j]));
            v[2 * j] = lo; v[2 * j + 1] = hi;
        }
        float4* xwp = (float4*)&XW[(size_t)gr * HD + c0];
        xwp[0] = make_float4(v[0], v[1], v[2], v[3]);
        xwp[1] = make_float4(v[4], v[5], v[6], v[7]);
        h4* xhp = (h4*)&XWH[(size_t)gr * HD + c0];
        h4 h0, h1;
        h0.a = __floats2half2_rn(v[0], v[1]);
        h0.b = __floats2half2_rn(v[2], v[3]);
        h1.a = __floats2half2_rn(v[4], v[5]);
        h1.b = __floats2half2_rn(v[6], v[7]);
        xhp[0] = h0; xhp[1] = h1;
    }
}

// ---------------- aggregation ------------------------------------------------
// out[d] = b + dis[d]^2 * xw[d] + sum norm_e * xwh[src_e]   (gathers in fp16)
__global__ void __launch_bounds__(256)
aggregate_kernel(const float* __restrict__ bias,
                 const float* __restrict__ xw,
                 const __half* __restrict__ xwh,
                 float* __restrict__ out, int n)
{
    int node = blockIdx.x * 8 + (threadIdx.x >> 5);
    int lane = threadIdx.x & 31;
    if (node >= n) return;

    int beg = g_rowptr[node];
    int end = g_rowptr[node + 1];

    float ds = g_dis[node];
    float sc = ds * ds;
    float4 vs = ((const float4*)(xw + (size_t)node * HD))[lane];
    float4 b4 = ((const float4*)bias)[lane];
    float4 acc;
    acc.x = fmaf(sc, vs.x, b4.x);
    acc.y = fmaf(sc, vs.y, b4.y);
    acc.z = fmaf(sc, vs.z, b4.z);
    acc.w = fmaf(sc, vs.w, b4.w);

    int p = beg;
    for (; p + 4 <= end; p += 4) {
        int2 e0 = g_csr[p + 0];
        int2 e1 = g_csr[p + 1];
        int2 e2 = g_csr[p + 2];
        int2 e3 = g_csr[p + 3];
        h4 h0 = ((const h4*)(xwh + (size_t)e0.x * HD))[lane];
        h4 h1 = ((const h4*)(xwh + (size_t)e1.x * HD))[lane];
        h4 h2 = ((const h4*)(xwh + (size_t)e2.x * HD))[lane];
        h4 h3 = ((const h4*)(xwh + (size_t)e3.x * HD))[lane];
        float n0 = __int_as_float(e0.y), n1 = __int_as_float(e1.y);
        float n2 = __int_as_float(e2.y), n3 = __int_as_float(e3.y);
        float2 a0 = __half22float2(h0.a), b0 = __half22float2(h0.b);
        float2 a1 = __half22float2(h1.a), b1 = __half22float2(h1.b);
        float2 a2 = __half22float2(h2.a), b2 = __half22float2(h2.b);
        float2 a3 = __half22float2(h3.a), b3 = __half22float2(h3.b);
        acc.x = fmaf(n0, a0.x, acc.x); acc.y = fmaf(n0, a0.y, acc.y);
        acc.z = fmaf(n0, b0.x, acc.z); acc.w = fmaf(n0, b0.y, acc.w);
        acc.x = fmaf(n1, a1.x, acc.x); acc.y = fmaf(n1, a1.y, acc.y);
        acc.z = fmaf(n1, b1.x, acc.z); acc.w = fmaf(n1, b1.y, acc.w);
        acc.x = fmaf(n2, a2.x, acc.x); acc.y = fmaf(n2, a2.y, acc.y);
        acc.z = fmaf(n2, b2.x, acc.z); acc.w = fmaf(n2, b2.y, acc.w);
        acc.x = fmaf(n3, a3.x, acc.x); acc.y = fmaf(n3, a3.y, acc.y);
        acc.z = fmaf(n3, b3.x, acc.z); acc.w = fmaf(n3, b3.y, acc.w);
    }
    for (; p < end; p++) {
        int2 e = g_csr[p];
        h4 hv = ((const h4*)(xwh + (size_t)e.x * HD))[lane];
        float nm = __int_as_float(e.y);
        float2 fa = __half22float2(hv.a), fb = __half22float2(hv.b);
        acc.x = fmaf(nm, fa.x, acc.x); acc.y = fmaf(nm, fa.y, acc.y);
        acc.z = fmaf(nm, fb.x, acc.z); acc.w = fmaf(nm, fb.y, acc.w);
    }

    ((float4*)(out + (size_t)node * HD))[lane] = acc;
}

// ---------------- launch ----------------------------------------------------
extern "C" void kernel_launch(void* const* d_in, const int* in_sizes, int n_in,
                              void* d_out, int out_size) {
    const float* emb = (const float*)d_in[0];
    const int*   ew  = (const int*)d_in[1];   // width detected on device
    const float* W1  = (const float*)d_in[2];
    const float* b1  = (const float*)d_in[3];
    const float* W2  = (const float*)d_in[4];
    const float* b2  = (const float*)d_in[5];
    float* out = (float*)d_out;

    const int nrows = in_sizes[0] / HD;       // 50000
    const int E     = in_sizes[1] / 2;        // 600000

    float *xw_p, *h1_p;
    __half* xwh_p;
    cudaGetSymbolAddress((void**)&xw_p,  g_xw);
    cudaGetSymbolAddress((void**)&xwh_p, g_xwh);
    cudaGetSymbolAddress((void**)&h1_p,  g_h1);

    cudaFuncSetAttribute(gcn_gemm, cudaFuncAttributeMaxDynamicSharedMemorySize,
                         GEMM_SMEM_BYTES);

    // Side stream + events (created once on the first, non-captured call).
    static cudaStream_t s_side = nullptr;
    static cudaEvent_t  s_ev0 = nullptr, s_ev1 = nullptr;
    if (s_side == nullptr) {
        cudaStreamCreateWithFlags(&s_side, cudaStreamNonBlocking);
        cudaEventCreateWithFlags(&s_ev0, cudaEventDisableTiming);
        cudaEventCreateWithFlags(&s_ev1, cudaEventDisableTiming);
    }

    const int nb_nodes = (nrows + 255) / 256;   // 196
    const int nb_edges = (E + 255) / 256;       // 2344
    const int nb_gemm  = (nrows + 127) / 128;   // 391
    const int nb_agg   = (nrows + 7) / 8;       // 6250

    // ---- fork: layer-1 GEMM on side stream, CSR build on main stream ----
    cudaEventRecord(s_ev0, 0);
    cudaStreamWaitEvent(s_side, s_ev0, 0);
    gcn_gemm<<<nb_gemm, 256, GEMM_SMEM_BYTES, s_side>>>(emb, W1, xw_p, xwh_p, nrows);
    cudaEventRecord(s_ev1, s_side);

    initdetect_kernel<<<nb_nodes, 256>>>(ew, nrows);
    hist_kernel<<<nb_edges, 256>>>(ew, E);
    scanA_kernel<<<nb_nodes, 256>>>(nrows);
    scanB_kernel<<<1, 256>>>(nb_nodes);
    scanC_kernel<<<nb_nodes, 256>>>(nrows, E);
    fill_kernel<<<nb_edges, 256>>>(ew, E);

    // ---- join, then serial tail ----
    cudaStreamWaitEvent(0, s_ev1, 0);
    aggregate_kernel<<<nb_agg, 256>>>(b1, xw_p, xwh_p, h1_p, nrows);
    gcn_gemm<<<nb_gemm, 256, GEMM_SMEM_BYTES>>>(h1_p, W2, xw_p, xwh_p, nrows);
    aggregate_kernel<<<nb_agg, 256>>>(b2, xw_p, xwh_p, out, nrows);
}

// round 12
// speedup vs baseline: 2.0310x; 1.6173x over previous
#include <cuda_runtime.h>
#include <cuda_fp16.h>
#include <cuda_bf16.h>
#include <cstdint>

#define N_NODES 50000
#define HD 128
#define E_MAX 600000

// ---------------- scratch (device globals; no dynamic allocation) ----------
__device__ float  g_dis[N_NODES];                 // rsqrt(degree incl. self-loop)
__device__ int    g_cnt[N_NODES];                 // in-degree histogram (edges only)
__device__ int    g_rowptr[N_NODES + 1];          // CSR row pointers
__device__ int    g_cursor[N_NODES];              // fill cursors
__device__ int    g_bsum[256];                    // scan block sums
__device__ int2   g_csr[E_MAX];                   // packed (src, norm), dst-sorted
__device__ __half g_xwh[(size_t)N_NODES * HD];    // x @ W^T (fp16)
__device__ float  g_h1[(size_t)N_NODES * HD];     // layer-1 output (fp32)
__device__ int    g_is64;                         // 1 if edge_index stored as int64

struct __align__(8) h4 { __half2 a, b; };

// ---------------- init + dtype detect (merged) ------------------------------
__global__ void initdetect_kernel(const int* __restrict__ ew, int n) {
    int i = blockIdx.x * blockDim.x + threadIdx.x;
    if (i < n) g_cnt[i] = 0;
    if (blockIdx.x == 0) {
        __shared__ int found;
        if (threadIdx.x == 0) found = 0;
        __syncthreads();
        int f = 0;
        for (int j = threadIdx.x; j < 2048; j += blockDim.x)
            if (ew[2 * j + 1] != 0) f = 1;
        if (f) atomicOr(&found, 1);
        __syncthreads();
        if (threadIdx.x == 0) g_is64 = found ? 0 : 1;
    }
}

__global__ void hist_kernel(const int* __restrict__ ew, int E) {
    int e = blockIdx.x * blockDim.x + threadIdx.x;
    if (e >= E) return;
    int d = g_is64 ? ew[2 * (E + e)] : ew[E + e];
    atomicAdd(&g_cnt[d], 1);
}

// ---- exclusive scan of g_cnt -> g_rowptr (3 kernels); also emits g_dis ----
__global__ void scanA_kernel(int n) {
    __shared__ int sm[256];
    int i = blockIdx.x * 256 + threadIdx.x;
    int v = (i < n) ? g_cnt[i] : 0;
    if (i < n) g_dis[i] = rsqrtf((float)(v + 1));
    sm[threadIdx.x] = v;
    __syncthreads();
    #pragma unroll
    for (int off = 1; off < 256; off <<= 1) {
        int t = (threadIdx.x >= off) ? sm[threadIdx.x - off] : 0;
        __syncthreads();
        sm[threadIdx.x] += t;
        __syncthreads();
    }
    if (i < n) g_rowptr[i] = sm[threadIdx.x] - v;
    if (threadIdx.x == 255) g_bsum[blockIdx.x] = sm[255];
}

__global__ void scanB_kernel(int nb) {
    __shared__ int sm[256];
    int v = (threadIdx.x < nb) ? g_bsum[threadIdx.x] : 0;
    sm[threadIdx.x] = v;
    __syncthreads();
    #pragma unroll
    for (int off = 1; off < 256; off <<= 1) {
        int t = (threadIdx.x >= off) ? sm[threadIdx.x - off] : 0;
        __syncthreads();
        sm[threadIdx.x] += t;
        __syncthreads();
    }
    if (threadIdx.x < nb) g_bsum[threadIdx.x] = sm[threadIdx.x] - v;
}

__global__ void scanC_kernel(int n, int E) {
    int i = blockIdx.x * 256 + threadIdx.x;
    if (i < n) {
        int rp = g_rowptr[i] + g_bsum[blockIdx.x];
        g_rowptr[i] = rp;
        g_cursor[i] = rp;
    }
    if (i == 0) g_rowptr[n] = E;
}

__global__ void fill_kernel(const int* __restrict__ ew, int E) {
    int e = blockIdx.x * blockDim.x + threadIdx.x;
    if (e >= E) return;
    int s, d;
    if (g_is64) { s = ew[2 * e]; d = ew[2 * (E + e)]; }
    else        { s = ew[e];     d = ew[E + e]; }
    int pos = atomicAdd(&g_cursor[d], 1);
    float nm = g_dis[s] * g_dis[d];
    g_csr[pos] = make_int2(s, __float_as_int(nm));
}

// =========== tensor-core GEMM: XWH = fp16(X @ W^T), bf16 split ============
// mma.sync.m16n8k16 bf16 (plain PTX, works on bare sm_103 target).
// 2-term split x = hi + lo; 3 passes (hi*hi + hi*lo + lo*hi) into fp32 acc.
// CTA tile 128x128, K-tiles of 64. Smem: Ahi/Alo/Bhi/Blo [128][64] bf16,
// SW128-swizzled (128B rows). 8 warps: warp_m = wid&3 (32 rows), warp_n =
// wid>>2 (64 cols). occ 2.
#define GEMM_SMEM_BYTES 65536
#define AHI_OFF 0
#define ALO_OFF 16384
#define BHI_OFF 32768
#define BLO_OFF 49152

static __device__ __forceinline__ uint32_t smem_u32(const void* p) {
    uint32_t a;
    asm("{ .reg .u64 t; cvta.to.shared.u64 t, %1; cvt.u32.u64 %0, t; }"
        : "=r"(a) : "l"(p));
    return a;
}

// byte offset of 16B chunk `c` (0..7) in swizzled row `r` of a [128][64]bf16 tile
static __device__ __forceinline__ uint32_t sw_off(int r, int c) {
    return (uint32_t)(r * 128 + (((c) << 4) ^ ((r & 7) << 4)));
}

static __device__ __forceinline__ void split_pair(float x, float y,
                                                  uint32_t& hi, uint32_t& lo) {
    __nv_bfloat162 h = __floats2bfloat162_rn(x, y);
    __nv_bfloat162 l = __floats2bfloat162_rn(x - __bfloat162float(h.x),
                                             y - __bfloat162float(h.y));
    hi = *reinterpret_cast<uint32_t*>(&h);
    lo = *reinterpret_cast<uint32_t*>(&l);
}

#define LDSM_X4(r, addr) \
    asm volatile("ldmatrix.sync.aligned.m8n8.x4.shared.b16 {%0,%1,%2,%3}, [%4];" \
                 : "=r"((r)[0]), "=r"((r)[1]), "=r"((r)[2]), "=r"((r)[3]) : "r"(addr))
#define LDSM_X2(r, addr) \
    asm volatile("ldmatrix.sync.aligned.m8n8.x2.shared.b16 {%0,%1}, [%2];" \
                 : "=r"((r)[0]), "=r"((r)[1]) : "r"(addr))
#define MMA_BF16(d, a, b) \
    asm volatile("mma.sync.aligned.m16n8k16.row.col.f32.bf16.bf16.f32 " \
                 "{%0,%1,%2,%3}, {%4,%5,%6,%7}, {%8,%9}, {%0,%1,%2,%3};" \
                 : "+f"((d)[0]), "+f"((d)[1]), "+f"((d)[2]), "+f"((d)[3]) \
                 : "r"((a)[0]), "r"((a)[1]), "r"((a)[2]), "r"((a)[3]), \
                   "r"((b)[0]), "r"((b)[1]))

__global__ void __launch_bounds__(256, 2)
gcn_gemm(const float* __restrict__ X, const float* __restrict__ W,
         __half* __restrict__ XWH, int nrows)
{
    extern __shared__ char smem[];
    const uint32_t smb = smem_u32(smem);
    const int tid = threadIdx.x;
    const int lane = tid & 31;
    const int wid = tid >> 5;
    const int warp_m = wid & 3;
    const int warp_n = wid >> 2;
    const int row0 = blockIdx.x * 128;

    float acc[2][8][4];
    #pragma unroll
    for (int mi = 0; mi < 2; mi++)
        #pragma unroll
        for (int nj = 0; nj < 8; nj++)
            #pragma unroll
            for (int q = 0; q < 4; q++) acc[mi][nj][q] = 0.f;

    const int arow = lane & 15;         // A ldmatrix row-in-tile
    const int akh  = lane >> 4;         // A k-half (16B)
    const int brow = lane & 7;          // B ldmatrix row-in-tile
    const int bkh  = (lane >> 3) & 1;   // B k-half

    #pragma unroll
    for (int t = 0; t < 2; t++) {
        const int k0 = t * 64;

        // ---- load + split X and W tiles into swizzled bf16 smem ----
        #pragma unroll
        for (int it = 0; it < 4; it++) {
            int id = tid + 256 * it;          // 0..1023
            int r = id >> 3, c8 = id & 7;     // row, 16B chunk (8 elems)
            uint32_t so = sw_off(r, c8);
            // X row (zero-pad OOB rows)
            int gr = row0 + r;
            float4 xa = make_float4(0.f, 0.f, 0.f, 0.f), xb = xa;
            if (gr < nrows) {
                const float4* xp = (const float4*)(X + (size_t)gr * HD + k0 + c8 * 8);
                xa = xp[0]; xb = xp[1];
            }
            uint4 hi4, lo4;
            split_pair(xa.x, xa.y, hi4.x, lo4.x);
            split_pair(xa.z, xa.w, hi4.y, lo4.y);
            split_pair(xb.x, xb.y, hi4.z, lo4.z);
            split_pair(xb.z, xb.w, hi4.w, lo4.w);
            *(uint4*)(smem + AHI_OFF + so) = hi4;
            *(uint4*)(smem + ALO_OFF + so) = lo4;
            // W row
            const float4* wp = (const float4*)(W + (size_t)r * HD + k0 + c8 * 8);
            float4 wa = wp[0], wb = wp[1];
            split_pair(wa.x, wa.y, hi4.x, lo4.x);
            split_pair(wa.z, wa.w, hi4.y, lo4.y);
            split_pair(wb.x, wb.y, hi4.z, lo4.z);
            split_pair(wb.z, wb.w, hi4.w, lo4.w);
            *(uint4*)(smem + BHI_OFF + so) = hi4;
            *(uint4*)(smem + BLO_OFF + so) = lo4;
        }
        __syncthreads();

        // ---- 4 k-chunks of 16 ----
        #pragma unroll
        for (int kc = 0; kc < 4; kc++) {
            uint32_t ahi[2][4], alo[2][4];
            #pragma unroll
            for (int mi = 0; mi < 2; mi++) {
                int rr = warp_m * 32 + mi * 16 + arow;
                uint32_t off = sw_off(rr, 2 * kc + akh);
                LDSM_X4(ahi[mi], smb + AHI_OFF + off);
                LDSM_X4(alo[mi], smb + ALO_OFF + off);
            }
            #pragma unroll
            for (int nj = 0; nj < 8; nj++) {
                int nr = warp_n * 64 + nj * 8 + brow;
                uint32_t boff = sw_off(nr, 2 * kc + bkh);
                uint32_t bh[2], bl[2];
                LDSM_X2(bh, smb + BHI_OFF + boff);
                LDSM_X2(bl, smb + BLO_OFF + boff);
                #pragma unroll
                for (int mi = 0; mi < 2; mi++) {
                    MMA_BF16(acc[mi][nj], ahi[mi], bh);
                    MMA_BF16(acc[mi][nj], ahi[mi], bl);
                    MMA_BF16(acc[mi][nj], alo[mi], bh);
                }
            }
        }
        __syncthreads();
    }

    // ---- epilogue: fp32 acc -> fp16 XWH ----
    const int gr0 = lane >> 2;
    const int gc0 = (lane & 3) * 2;
    #pragma unroll
    for (int mi = 0; mi < 2; mi++) {
        #pragma unroll
        for (int nj = 0; nj < 8; nj++) {
            int cc = warp_n * 64 + nj * 8 + gc0;
            int r1 = row0 + warp_m * 32 + mi * 16 + gr0;
            if (r1 < nrows) {
                __half2 h = __floats2half2_rn(acc[mi][nj][0], acc[mi][nj][1]);
                *(__half2*)&XWH[(size_t)r1 * HD + cc] = h;
            }
            int r2 = r1 + 8;
            if (r2 < nrows) {
                __half2 h = __floats2half2_rn(acc[mi][nj][2], acc[mi][nj][3]);
                *(__half2*)&XWH[(size_t)r2 * HD + cc] = h;
            }
        }
    }
}

// ---------------- aggregation ------------------------------------------------
// out[d] = b + dis[d]^2 * xwh[d] + sum norm_e * xwh[src_e]   (all fp16 reads)
__global__ void __launch_bounds__(256)
aggregate_kernel(const float* __restrict__ bias,
                 const __half* __restrict__ xwh,
                 float* __restrict__ out, int n)
{
    int node = blockIdx.x * 8 + (threadIdx.x >> 5);
    int lane = threadIdx.x & 31;
    if (node >= n) return;

    int beg = g_rowptr[node];
    int end = g_rowptr[node + 1];

    float ds = g_dis[node];
    float sc = ds * ds;
    h4 hs = ((const h4*)(xwh + (size_t)node * HD))[lane];
    float2 s0 = __half22float2(hs.a), s1 = __half22float2(hs.b);
    float4 b4 = ((const float4*)bias)[lane];
    float4 acc;
    acc.x = fmaf(sc, s0.x, b4.x);
    acc.y = fmaf(sc, s0.y, b4.y);
    acc.z = fmaf(sc, s1.x, b4.z);
    acc.w = fmaf(sc, s1.y, b4.w);

    int p = beg;
    for (; p + 4 <= end; p += 4) {
        int2 e0 = g_csr[p + 0];
        int2 e1 = g_csr[p + 1];
        int2 e2 = g_csr[p + 2];
        int2 e3 = g_csr[p + 3];
        h4 h0 = ((const h4*)(xwh + (size_t)e0.x * HD))[lane];
        h4 h1 = ((const h4*)(xwh + (size_t)e1.x * HD))[lane];
        h4 h2 = ((const h4*)(xwh + (size_t)e2.x * HD))[lane];
        h4 h3 = ((const h4*)(xwh + (size_t)e3.x * HD))[lane];
        float n0 = __int_as_float(e0.y), n1 = __int_as_float(e1.y);
        float n2 = __int_as_float(e2.y), n3 = __int_as_float(e3.y);
        float2 a0 = __half22float2(h0.a), b0 = __half22float2(h0.b);
        float2 a1 = __half22float2(h1.a), b1 = __half22float2(h1.b);
        float2 a2 = __half22float2(h2.a), b2 = __half22float2(h2.b);
        float2 a3 = __half22float2(h3.a), b3 = __half22float2(h3.b);
        acc.x = fmaf(n0, a0.x, acc.x); acc.y = fmaf(n0, a0.y, acc.y);
        acc.z = fmaf(n0, b0.x, acc.z); acc.w = fmaf(n0, b0.y, acc.w);
        acc.x = fmaf(n1, a1.x, acc.x); acc.y = fmaf(n1, a1.y, acc.y);
        acc.z = fmaf(n1, b1.x, acc.z); acc.w = fmaf(n1, b1.y, acc.w);
        acc.x = fmaf(n2, a2.x, acc.x); acc.y = fmaf(n2, a2.y, acc.y);
        acc.z = fmaf(n2, b2.x, acc.z); acc.w = fmaf(n2, b2.y, acc.w);
        acc.x = fmaf(n3, a3.x, acc.x); acc.y = fmaf(n3, a3.y, acc.y);
        acc.z = fmaf(n3, b3.x, acc.z); acc.w = fmaf(n3, b3.y, acc.w);
    }
    for (; p < end; p++) {
        int2 e = g_csr[p];
        h4 hv = ((const h4*)(xwh + (size_t)e.x * HD))[lane];
        float nm = __int_as_float(e.y);
        float2 fa = __half22float2(hv.a), fb = __half22float2(hv.b);
        acc.x = fmaf(nm, fa.x, acc.x); acc.y = fmaf(nm, fa.y, acc.y);
        acc.z = fmaf(nm, fb.x, acc.z); acc.w = fmaf(nm, fb.y, acc.w);
    }

    ((float4*)(out + (size_t)node * HD))[lane] = acc;
}

// ---------------- launch ----------------------------------------------------
extern "C" void kernel_launch(void* const* d_in, const int* in_sizes, int n_in,
                              void* d_out, int out_size) {
    const float* emb = (const float*)d_in[0];
    const int*   ew  = (const int*)d_in[1];   // width detected on device
    const float* W1  = (const float*)d_in[2];
    const float* b1  = (const float*)d_in[3];
    const float* W2  = (const float*)d_in[4];
    const float* b2  = (const float*)d_in[5];
    float* out = (float*)d_out;

    const int nrows = in_sizes[0] / HD;       // 50000
    const int E     = in_sizes[1] / 2;        // 600000

    float* h1_p;
    __half* xwh_p;
    cudaGetSymbolAddress((void**)&xwh_p, g_xwh);
    cudaGetSymbolAddress((void**)&h1_p,  g_h1);

    cudaFuncSetAttribute(gcn_gemm, cudaFuncAttributeMaxDynamicSharedMemorySize,
                         GEMM_SMEM_BYTES);

    // Side stream + events (created once on the first, non-captured call).
    static cudaStream_t s_side = nullptr;
    static cudaEvent_t  s_ev0 = nullptr, s_ev1 = nullptr;
    if (s_side == nullptr) {
        cudaStreamCreateWithFlags(&s_side, cudaStreamNonBlocking);
        cudaEventCreateWithFlags(&s_ev0, cudaEventDisableTiming);
        cudaEventCreateWithFlags(&s_ev1, cudaEventDisableTiming);
    }

    const int nb_nodes = (nrows + 255) / 256;   // 196
    const int nb_edges = (E + 255) / 256;       // 2344
    const int nb_gemm  = (nrows + 127) / 128;   // 391
    const int nb_agg   = (nrows + 7) / 8;       // 6250

    // ---- fork: layer-1 GEMM on side stream, CSR build on main stream ----
    cudaEventRecord(s_ev0, 0);
    cudaStreamWaitEvent(s_side, s_ev0, 0);
    gcn_gemm<<<nb_gemm, 256, GEMM_SMEM_BYTES, s_side>>>(emb, W1, xwh_p, nrows);
    cudaEventRecord(s_ev1, s_side);

    initdetect_kernel<<<nb_nodes, 256>>>(ew, nrows);
    hist_kernel<<<nb_edges, 256>>>(ew, E);
    scanA_kernel<<<nb_nodes, 256>>>(nrows);
    scanB_kernel<<<1, 256>>>(nb_nodes);
    scanC_kernel<<<nb_nodes, 256>>>(nrows, E);
    fill_kernel<<<nb_edges, 256>>>(ew, E);

    // ---- join, then serial tail ----
    cudaStreamWaitEvent(0, s_ev1, 0);
    aggregate_kernel<<<nb_agg, 256>>>(b1, xwh_p, h1_p, nrows);
    gcn_gemm<<<nb_gemm, 256, GEMM_SMEM_BYTES>>>(h1_p, W2, xwh_p, nrows);
    aggregate_kernel<<<nb_agg, 256>>>(b2, xwh_p, out, nrows);
}